// round 5
// baseline (speedup 1.0000x reference)
#include <cuda_runtime.h>
#include <math.h>

#define LAGI 5
#define POLI 3
#define GRP_PER_BLK 16
#define THREADS 128
#define MROW 9                     // padded row stride in doubles (bank-conflict-free)
#define MMAT (8 * MROW)            // 72 doubles per matrix
#define MGRP (7 * MMAT)            // 504 doubles per batch-group (M2..M8)
#define F0ROW 9                    // padded f32 row stride
#define F0GRP (8 * F0ROW)          // 72 floats per group
#define SMEM_BYTES (GRP_PER_BLK * MGRP * 8 + GRP_PER_BLK * F0GRP * 4)

#define FULLM 0xffffffffu

__device__ __forceinline__ double dshfl(double v, int s) {
    return __shfl_sync(FULLM, v, s, 8);
}
__device__ __forceinline__ double dred(double v) {
    v += __shfl_xor_sync(FULLM, v, 4, 8);
    v += __shfl_xor_sync(FULLM, v, 2, 8);
    v += __shfl_xor_sync(FULLM, v, 1, 8);
    return v;
}
__device__ __forceinline__ float fshfl(float v, int s) {
    return __shfl_sync(FULLM, v, s, 8);
}
__device__ __forceinline__ float fred(float v) {
    v += __shfl_xor_sync(FULLM, v, 4, 8);
    v += __shfl_xor_sync(FULLM, v, 2, 8);
    v += __shfl_xor_sync(FULLM, v, 1, 8);
    return v;
}

__global__ void __launch_bounds__(THREADS, 3)
fleigh_kernel(const float* __restrict__ Aall, float* __restrict__ out, int B)
{
    extern __shared__ unsigned char smraw[];
    double* Msm = (double*)smraw;
    float*  Fsm = (float*)(smraw + (size_t)GRP_PER_BLK * MGRP * 8);

    int tid  = threadIdx.x;
    int lane = tid & 7;
    int grp  = tid >> 3;
    int b    = blockIdx.x * GRP_PER_BLK + grp;
    int bb   = (b < B) ? b : (B - 1);
    const float* Ap = Aall + (size_t)bb * 64;

    double* Mg = Msm + grp * MGRP;
    float*  Fg = Fsm + grp * F0GRP;

    // ---- f32 norm, linear over 64 (identical arithmetic to prior passing kernel) ----
    float nrm2 = 0.f;
    #pragma unroll
    for (int i = 0; i < 64; i++) {
        float v = Ap[i];
        nrm2 = __fadd_rn(nrm2, __fmul_rn(v, v));
    }
    double scale = (double)sqrtf(nrm2) / 2.8284271247461903;
    scale = fmax(scale, 1e-12);

    // ---- my row of As (f64 = f32 / f64scale) ----
    double Asr[8];
    {
        const float4* Ap4 = (const float4*)(Ap + lane * 8);
        float4 q0 = Ap4[0], q1 = Ap4[1];
        Asr[0] = (double)q0.x / scale; Asr[1] = (double)q0.y / scale;
        Asr[2] = (double)q0.z / scale; Asr[3] = (double)q0.w / scale;
        Asr[4] = (double)q1.x / scale; Asr[5] = (double)q1.y / scale;
        Asr[6] = (double)q1.z / scale; Asr[7] = (double)q1.w / scale;
    }

    // ---- Faddeev-LeVerrier: c coeffs; M_2..M_8 rows into shared ----
    double c[9];
    #pragma unroll
    for (int i = 0; i < 9; i++) c[i] = 0.0;
    c[8] = 1.0;

    double dmine = 0.0;                 // As[lane][lane]
    #pragma unroll
    for (int j = 0; j < 8; j++) if (lane == j) dmine = Asr[j];
    c[7] = -dred(dmine);

    {   // M2 = As + c7 I
        double cur[8];
        double tr = 0.0;
        #pragma unroll
        for (int j = 0; j < 8; j++) {
            cur[j] = Asr[j] + ((lane == j) ? c[7] : 0.0);
            tr += Asr[j] * cur[j];
        }
        c[6] = -dred(tr) / 2.0;
        #pragma unroll
        for (int j = 0; j < 8; j++) Mg[0 * MMAT + lane * MROW + j] = cur[j];
    }
    __syncwarp();

    #pragma unroll 1
    for (int k = 3; k <= 8; k++) {
        double ck = c[9 - k];
        double s[8];
        #pragma unroll
        for (int j = 0; j < 8; j++) s[j] = (lane == j) ? ck : 0.0;
        const double* prev = Mg + (k - 3) * MMAT;
        #pragma unroll
        for (int t = 0; t < 8; t++) {
            double w = Asr[t];
            #pragma unroll
            for (int j = 0; j < 8; j++) s[j] += w * prev[t * MROW + j];
        }
        double tr = 0.0;
        #pragma unroll
        for (int j = 0; j < 8; j++) tr += Asr[j] * s[j];
        c[8 - k] = -dred(tr) / (double)k;
        double* curp = Mg + (k - 2) * MMAT;
        #pragma unroll
        for (int j = 0; j < 8; j++) curp[lane * MROW + j] = s[j];
        __syncwarp();
    }

    // ---- initial guesses: sorted diagonal + linspace ----
    double zi[8];
    #pragma unroll
    for (int i = 0; i < 8; i++) zi[i] = dshfl(dmine, i);
    #pragma unroll 1
    for (int i = 1; i < 8; i++) {
        double key = zi[i];
        int j = i - 1;
        while (j >= 0 && zi[j] > key) { zi[j + 1] = zi[j]; j--; }
        zi[j + 1] = key;
    }
    const double lstep = 2e-4 / 7.0;

    // ---- Laguerre + deflation (replicated on all lanes, non-FMA) ----
    double cl[9];
    #pragma unroll
    for (int i = 0; i < 9; i++) cl[i] = c[i];
    double rootmine = 0.0;
    float  frmine = 0.f, stmine = 0.f;
    #pragma unroll 1
    for (int ri = 0; ri < 8; ri++) {
        int deg = 8 - ri;
        double dd = (double)deg;
        double z = __dadd_rn(zi[ri], __dadd_rn(-1e-4, __dmul_rn(lstep, (double)ri)));
        float fr = 0.f, st = (float)LAGI;
        #pragma unroll 1
        for (int it = 0; it < LAGI; it++) {
            double pv = cl[deg], dp = 0.0, d2 = 0.0;
            #pragma unroll 1
            for (int j = deg - 1; j >= 0; j--) {
                d2 = __dadd_rn(__dmul_rn(d2, z), dp);
                dp = __dadd_rn(__dmul_rn(dp, z), pv);
                pv = __dadd_rn(__dmul_rn(pv, z), cl[j]);
            }
            float dp_abs = (float)fabs(dp);
            fr = __fadd_rn(fr, 1.0f / __fadd_rn(dp_abs, 1e-8f));
            float pv_abs = (float)fabs(pv);
            if (pv_abs < 1e-6f && st == (float)LAGI) st = (float)it;
            bool ok = fabs(pv) > 1e-30;
            double ps = ok ? pv : 1.0;
            double G = ok ? (dp / ps) : 0.0;
            double GG = __dmul_rn(G, G);
            double twod2 = ok ? (__dmul_rn(2.0, d2) / ps) : 0.0;
            double H = __dadd_rn(GG, -twod2);
            double inner = __dadd_rn(__dmul_rn(dd, H), -GG);
            double disc = __dmul_rn(__dadd_rn(dd, -1.0), inner);
            disc = disc > 0.0 ? disc : 0.0;
            double sq = sqrt(disc);
            double gp = __dadd_rn(G, sq), gm = __dadd_rn(G, -sq);
            double den = (fabs(gp) >= fabs(gm)) ? gp : gm;
            bool dok = fabs(den) > 1e-20;
            double ds = dok ? den : 1.0;
            z = __dadd_rn(z, -(dok ? (dd / ds) : 0.0));
        }
        if (lane == ri) { rootmine = z; frmine = fr; stmine = st; }
        // deflation (non-FMA)
        double bcur = cl[deg];
        #pragma unroll 1
        for (int j = deg - 1; j >= 1; j--) {
            double tmp = cl[j];
            cl[j] = bcur;
            bcur = __dadd_rn(tmp, __dmul_rn(z, bcur));
        }
        cl[0] = bcur;
    }

    // ---- Newton polish: lane i polishes root i (parallel, non-FMA) ----
    #pragma unroll 1
    for (int p = 0; p < POLI; p++) {
        double r = rootmine;
        double pv = 1.0, dp = 0.0;
        #pragma unroll
        for (int j = 7; j >= 0; j--) {
            dp = __dadd_rn(__dmul_rn(dp, r), pv);
            pv = __dadd_rn(__dmul_rn(pv, r), c[j]);
        }
        if (fabs(dp) > 1e-30) r = __dadd_rn(r, -(pv / dp));
        rootmine = r;
    }

    // ---- adjugate Horner: per-eigvec column norms, best col, eigenvector ----
    float Vrow[8];     // V[lane][i]
    #pragma unroll 1
    for (int i = 0; i < 8; i++) {
        double lam = dshfl(rootmine, i);
        double rcol[8];
        #pragma unroll
        for (int col = 0; col < 8; col++) {
            double r = (lane == col) ? 1.0 : 0.0;
            #pragma unroll
            for (int s = 0; s < 7; s++)
                r = r * lam + Mg[s * MMAT + lane * MROW + col];
            rcol[col] = r;
        }
        double cn[8];
        #pragma unroll
        for (int col = 0; col < 8; col++) cn[col] = dred(rcol[col] * rcol[col]);
        int best = 0; double bv = cn[0];
        #pragma unroll
        for (int col = 1; col < 8; col++)
            if (cn[col] > bv) { bv = cn[col]; best = col; }
        double v = rcol[0];
        #pragma unroll
        for (int col = 1; col < 8; col++) if (best == col) v = rcol[col];
        double s2 = dred(v * v);
        double nrm = sqrt(s2) + 1e-30;
        Vrow[i] = (float)(v / nrm);
    }

    // ---- stage V, compute Y = V^T V ----
    #pragma unroll
    for (int j = 0; j < 8; j++) Fg[lane * F0ROW + j] = Vrow[j];
    __syncwarp();
    float Yrow[8], Xrow[8];
    #pragma unroll
    for (int j = 0; j < 8; j++) { Yrow[j] = 0.f; Xrow[j] = (lane == j) ? 1.f : 0.f; }
    #pragma unroll
    for (int a = 0; a < 8; a++) {
        float vai = Fg[a * F0ROW + lane];
        #pragma unroll
        for (int j = 0; j < 8; j++) Yrow[j] += vai * Fg[a * F0ROW + j];
    }

    // ---- Newton-Schulz (shfl-broadcast matmuls) ----
    #pragma unroll 1
    for (int ns = 0; ns < 2; ns++) {
        float Trow[8], Xn[8], Yn[8];
        #pragma unroll
        for (int j = 0; j < 8; j++) {
            Trow[j] = ((lane == j) ? 3.f : 0.f) - Yrow[j];
            Xn[j] = 0.f; Yn[j] = 0.f;
        }
        #pragma unroll
        for (int kk = 0; kk < 8; kk++) {
            float xk = Xrow[kk];
            float tk = Trow[kk];
            #pragma unroll
            for (int j = 0; j < 8; j++) {
                float tkj = fshfl(Trow[j], kk);
                float ykj = fshfl(Yrow[j], kk);
                Xn[j] += xk * tkj;
                Yn[j] += tk * ykj;
            }
        }
        #pragma unroll
        for (int j = 0; j < 8; j++) { Xrow[j] = 0.5f * Xn[j]; Yrow[j] = 0.5f * Yn[j]; }
    }
    {   // V = V @ X
        float Vn[8];
        #pragma unroll
        for (int j = 0; j < 8; j++) Vn[j] = 0.f;
        #pragma unroll
        for (int kk = 0; kk < 8; kk++) {
            float vk = Vrow[kk];
            #pragma unroll
            for (int j = 0; j < 8; j++) Vn[j] += vk * fshfl(Xrow[j], kk);
        }
        #pragma unroll
        for (int j = 0; j < 8; j++) Vrow[j] = Vn[j];
    }

    // ---- restage final V ----
    __syncwarp();
    #pragma unroll
    for (int j = 0; j < 8; j++) Fg[lane * F0ROW + j] = Vrow[j];
    __syncwarp();

    // ---- refinement residual ----
    float rrp = 0.f;
    #pragma unroll
    for (int j = 0; j < 8; j++) {
        float s = 0.f;
        #pragma unroll
        for (int a = 0; a < 8; a++) s += Fg[a * F0ROW + lane] * Fg[a * F0ROW + j];
        float d = s - ((lane == j) ? 1.f : 0.f);
        rrp += d * d;
    }
    float rr = sqrtf(fred(rrp));

    // ---- evals = diag(V^T A V) with original A ----
    float Afr[8];
    {
        const float4* Ap4 = (const float4*)(Ap + lane * 8);
        float4 q0 = Ap4[0], q1 = Ap4[1];
        Afr[0] = q0.x; Afr[1] = q0.y; Afr[2] = q0.z; Afr[3] = q0.w;
        Afr[4] = q1.x; Afr[5] = q1.y; Afr[6] = q1.z; Afr[7] = q1.w;
    }
    float evals[8];
    #pragma unroll
    for (int i = 0; i < 8; i++) {
        float av = 0.f;
        #pragma unroll
        for (int k = 0; k < 8; k++) av += Afr[k] * Fg[k * F0ROW + i];
        evals[i] = fred(Vrow[i] * av);
    }

    // ---- stable argsort ascending (replicated) ----
    int perm[8];
    #pragma unroll
    for (int i = 0; i < 8; i++) perm[i] = i;
    #pragma unroll 1
    for (int i = 1; i < 8; i++) {
        int key = perm[i];
        float kv = evals[key];
        int j = i - 1;
        while (j >= 0 && evals[perm[j]] > kv) { perm[j + 1] = perm[j]; j--; }
        perm[j + 1] = key;
    }

    // ---- outputs ----
    if (b < B) {
        size_t Bs = (size_t)B;
        float* o_se = out;
        float* o_sv = out + Bs * 8;
        float* o_cc = out + Bs * 72;
        float* o_fr = out + Bs * 80;
        float* o_st = out + Bs * 88;
        float* o_eo = out + Bs * 96;
        float* o_rr = out + Bs * 104;

        int p = perm[lane];
        o_se[(size_t)b * 8 + lane] = evals[p];
        o_cc[(size_t)b * 8 + lane] = (float)c[lane];
        o_fr[(size_t)b * 8 + lane] = __shfl_sync(FULLM, frmine, p, 8);
        o_st[(size_t)b * 8 + lane] = __shfl_sync(FULLM, stmine, p, 8);
        o_eo[(size_t)b * 8 + lane] = (float)lane;
        if (lane == 0) o_rr[b] = rr;

        float outv[8];
        #pragma unroll
        for (int i = 0; i < 8; i++) {
            int pi = perm[i];
            float myv = Fg[lane * F0ROW + pi];
            // deterministic argmax over components (first max wins, like jnp.argmax)
            float bvv = 0.f, sval = 0.f;
            #pragma unroll
            for (int a = 0; a < 8; a++) {
                float v = Fg[a * F0ROW + pi];
                float avv = fabsf(v);
                if (avv > bvv) { bvv = avv; sval = v; }
            }
            float sg = (sval > 0.f) ? 1.f : ((sval < 0.f) ? -1.f : 0.f);
            outv[i] = myv * sg;
        }
        float4* dst = (float4*)(o_sv + (size_t)b * 64 + lane * 8);
        dst[0] = make_float4(outv[0], outv[1], outv[2], outv[3]);
        dst[1] = make_float4(outv[4], outv[5], outv[6], outv[7]);
    }
}

extern "C" void kernel_launch(void* const* d_in, const int* in_sizes, int n_in,
                              void* d_out, int out_size)
{
    const float* A = (const float*)d_in[0];
    float* out = (float*)d_out;
    int B = in_sizes[0] / 64;
    int blocks = (B + GRP_PER_BLK - 1) / GRP_PER_BLK;
    cudaFuncSetAttribute(fleigh_kernel,
                         cudaFuncAttributeMaxDynamicSharedMemorySize, SMEM_BYTES);
    fleigh_kernel<<<blocks, THREADS, SMEM_BYTES>>>(A, out, B);
}

// round 6
// speedup vs baseline: 1.8073x; 1.8073x over previous
#include <cuda_runtime.h>
#include <math.h>

#define LAGI 5
#define POLI 3
#define BMAX 65536
#define GPB 16
#define THREADS 128
#define FULLM 0xffffffffu

__device__ double g_c[BMAX * 9];
__device__ double g_zi[BMAX * 8];
__device__ double g_roots[BMAX * 8];
__device__ float  g_fs[BMAX * 16];

__device__ __forceinline__ double dshfl(double v, int s) {
    return __shfl_sync(FULLM, v, s, 8);
}
__device__ __forceinline__ double dred(double v) {
    v += __shfl_xor_sync(FULLM, v, 4, 8);
    v += __shfl_xor_sync(FULLM, v, 2, 8);
    v += __shfl_xor_sync(FULLM, v, 1, 8);
    return v;
}
__device__ __forceinline__ float fshfl(float v, int s) {
    return __shfl_sync(FULLM, v, s, 8);
}
__device__ __forceinline__ float fred(float v) {
    v += __shfl_xor_sync(FULLM, v, 4, 8);
    v += __shfl_xor_sync(FULLM, v, 2, 8);
    v += __shfl_xor_sync(FULLM, v, 1, 8);
    return v;
}

// ============================================================
// K1: Faddeev-LeVerrier (8 lanes/batch) -> c, zi, char_coeffs
// ============================================================
__global__ void __launch_bounds__(THREADS)
k1_fl(const float* __restrict__ Aall, float* __restrict__ out, int B)
{
    __shared__ double Msh[GPB][72];

    int tid = threadIdx.x, lane = tid & 7, grp = tid >> 3;
    int b = blockIdx.x * GPB + grp;
    int bb = (b < B) ? b : (B - 1);
    const float* Ap = Aall + (size_t)bb * 64;
    double* Mg = Msh[grp];

    float nrm2 = 0.f;
    #pragma unroll
    for (int i = 0; i < 64; i++) {
        float v = Ap[i];
        nrm2 = __fadd_rn(nrm2, __fmul_rn(v, v));
    }
    double scale = (double)sqrtf(nrm2) / 2.8284271247461903;
    scale = fmax(scale, 1e-12);

    double Asr[8];
    {
        const float4* Ap4 = (const float4*)(Ap + lane * 8);
        float4 q0 = Ap4[0], q1 = Ap4[1];
        Asr[0] = (double)q0.x / scale; Asr[1] = (double)q0.y / scale;
        Asr[2] = (double)q0.z / scale; Asr[3] = (double)q0.w / scale;
        Asr[4] = (double)q1.x / scale; Asr[5] = (double)q1.y / scale;
        Asr[6] = (double)q1.z / scale; Asr[7] = (double)q1.w / scale;
    }

    double c[9];
    #pragma unroll
    for (int i = 0; i < 9; i++) c[i] = 0.0;
    c[8] = 1.0;

    double dmine = 0.0;
    #pragma unroll
    for (int j = 0; j < 8; j++) if (lane == j) dmine = Asr[j];
    c[7] = -dred(dmine);

    {
        double tr = 0.0;
        #pragma unroll
        for (int j = 0; j < 8; j++) {
            double v = Asr[j] + ((lane == j) ? c[7] : 0.0);
            Mg[lane * 9 + j] = v;
            tr += Asr[j] * v;
        }
        c[6] = -dred(tr) / 2.0;
    }
    __syncwarp();

    #pragma unroll 1
    for (int k = 3; k <= 8; k++) {
        double ck = c[9 - k];
        double s[8];
        #pragma unroll
        for (int j = 0; j < 8; j++) s[j] = (lane == j) ? ck : 0.0;
        #pragma unroll
        for (int t = 0; t < 8; t++) {
            double w = Asr[t];
            #pragma unroll
            for (int j = 0; j < 8; j++) s[j] += w * Mg[t * 9 + j];
        }
        double tr = 0.0;
        #pragma unroll
        for (int j = 0; j < 8; j++) tr += Asr[j] * s[j];
        c[8 - k] = -dred(tr) / (double)k;
        __syncwarp();
        #pragma unroll
        for (int j = 0; j < 8; j++) Mg[lane * 9 + j] = s[j];
        __syncwarp();
    }

    double zi[8];
    #pragma unroll
    for (int i = 0; i < 8; i++) zi[i] = dshfl(dmine, i);
    #pragma unroll 1
    for (int i = 1; i < 8; i++) {
        double key = zi[i];
        int j = i - 1;
        while (j >= 0 && zi[j] > key) { zi[j + 1] = zi[j]; j--; }
        zi[j + 1] = key;
    }

    if (b < B && lane == 0) {
        #pragma unroll
        for (int i = 0; i < 9; i++) g_c[(size_t)b * 9 + i] = c[i];
        #pragma unroll
        for (int i = 0; i < 8; i++) g_zi[(size_t)b * 8 + i] = zi[i];
        float* o_cc = out + (size_t)B * 72;
        #pragma unroll
        for (int i = 0; i < 8; i++) o_cc[(size_t)b * 8 + i] = (float)c[i];
    }
}

// ============================================================
// K2: Laguerre + deflation + polish (1 thread/batch)
// ============================================================
__global__ void __launch_bounds__(128)
k2_lag(int B)
{
    int b = blockIdx.x * blockDim.x + threadIdx.x;
    if (b >= B) return;

    double c[9], cl[9], zi[8];
    #pragma unroll
    for (int i = 0; i < 9; i++) { c[i] = g_c[(size_t)b * 9 + i]; cl[i] = c[i]; }
    #pragma unroll
    for (int i = 0; i < 8; i++) zi[i] = g_zi[(size_t)b * 8 + i];

    const double lstep = 2e-4 / 7.0;
    double roots[8];
    float fric[8], sett[8];

    #pragma unroll
    for (int ri = 0; ri < 8; ri++) {
        const int deg = 8 - ri;
        const double dd = (double)deg;
        double z = __dadd_rn(zi[ri], __dadd_rn(-1e-4, __dmul_rn(lstep, (double)ri)));
        float fr = 0.f, st = (float)LAGI;
        #pragma unroll
        for (int it = 0; it < LAGI; it++) {
            double pv = cl[deg], dp = 0.0, d2 = 0.0;
            #pragma unroll
            for (int j = deg - 1; j >= 0; j--) {
                d2 = __dadd_rn(__dmul_rn(d2, z), dp);
                dp = __dadd_rn(__dmul_rn(dp, z), pv);
                pv = __dadd_rn(__dmul_rn(pv, z), cl[j]);
            }
            float dp_abs = (float)fabs(dp);
            fr = __fadd_rn(fr, 1.0f / __fadd_rn(dp_abs, 1e-8f));
            float pv_abs = (float)fabs(pv);
            if (pv_abs < 1e-6f && st == (float)LAGI) st = (float)it;
            bool ok = fabs(pv) > 1e-30;
            double ps = ok ? pv : 1.0;
            double G = ok ? (dp / ps) : 0.0;
            double GG = __dmul_rn(G, G);
            double twod2 = ok ? (__dmul_rn(2.0, d2) / ps) : 0.0;
            double H = __dadd_rn(GG, -twod2);
            double inner = __dadd_rn(__dmul_rn(dd, H), -GG);
            double disc = __dmul_rn(__dadd_rn(dd, -1.0), inner);
            disc = disc > 0.0 ? disc : 0.0;
            double sq = sqrt(disc);
            double gp = __dadd_rn(G, sq), gm = __dadd_rn(G, -sq);
            double den = (fabs(gp) >= fabs(gm)) ? gp : gm;
            bool dok = fabs(den) > 1e-20;
            double ds = dok ? den : 1.0;
            z = __dadd_rn(z, -(dok ? (dd / ds) : 0.0));
        }
        roots[ri] = z; fric[ri] = fr; sett[ri] = st;
        double bcur = cl[deg];
        #pragma unroll
        for (int j = deg - 1; j >= 1; j--) {
            double tmp = cl[j];
            cl[j] = bcur;
            bcur = __dadd_rn(tmp, __dmul_rn(z, bcur));
        }
        cl[0] = bcur;
    }

    #pragma unroll
    for (int p = 0; p < POLI; p++) {
        #pragma unroll
        for (int i = 0; i < 8; i++) {
            double r = roots[i];
            double pv = 1.0, dp = 0.0;
            #pragma unroll
            for (int j = 7; j >= 0; j--) {
                dp = __dadd_rn(__dmul_rn(dp, r), pv);
                pv = __dadd_rn(__dmul_rn(pv, r), c[j]);
            }
            if (fabs(dp) > 1e-30) r = __dadd_rn(r, -(pv / dp));
            roots[i] = r;
        }
    }

    #pragma unroll
    for (int i = 0; i < 8; i++) g_roots[(size_t)b * 8 + i] = roots[i];
    #pragma unroll
    for (int i = 0; i < 8; i++) {
        g_fs[(size_t)b * 16 + i]     = fric[i];
        g_fs[(size_t)b * 16 + 8 + i] = sett[i];
    }
}

// ============================================================
// K3: FL recompute (M rows in regs) + eigvec + NS + outputs
// ============================================================
__global__ void __launch_bounds__(THREADS)
k3_vec(const float* __restrict__ Aall, float* __restrict__ out, int B)
{
    __shared__ double Msh[GPB][72];
    __shared__ float  Fsh[GPB][72];

    int tid = threadIdx.x, lane = tid & 7, grp = tid >> 3;
    int b = blockIdx.x * GPB + grp;
    int bb = (b < B) ? b : (B - 1);
    const float* Ap = Aall + (size_t)bb * 64;
    double* Mg = Msh[grp];
    float*  Fg = Fsh[grp];

    float nrm2 = 0.f;
    #pragma unroll
    for (int i = 0; i < 64; i++) {
        float v = Ap[i];
        nrm2 = __fadd_rn(nrm2, __fmul_rn(v, v));
    }
    double scale = (double)sqrtf(nrm2) / 2.8284271247461903;
    scale = fmax(scale, 1e-12);

    double Asr[8];
    float Afr[8];
    {
        const float4* Ap4 = (const float4*)(Ap + lane * 8);
        float4 q0 = Ap4[0], q1 = Ap4[1];
        Afr[0] = q0.x; Afr[1] = q0.y; Afr[2] = q0.z; Afr[3] = q0.w;
        Afr[4] = q1.x; Afr[5] = q1.y; Afr[6] = q1.z; Afr[7] = q1.w;
        #pragma unroll
        for (int j = 0; j < 8; j++) Asr[j] = (double)Afr[j] / scale;
    }

    double Mrows[7][8];
    double c[9];
    #pragma unroll
    for (int i = 0; i < 9; i++) c[i] = 0.0;
    c[8] = 1.0;
    double dmine = 0.0;
    #pragma unroll
    for (int j = 0; j < 8; j++) if (lane == j) dmine = Asr[j];
    c[7] = -dred(dmine);
    {
        double tr = 0.0;
        #pragma unroll
        for (int j = 0; j < 8; j++) {
            double v = Asr[j] + ((lane == j) ? c[7] : 0.0);
            Mrows[0][j] = v;
            Mg[lane * 9 + j] = v;
            tr += Asr[j] * v;
        }
        c[6] = -dred(tr) / 2.0;
    }
    __syncwarp();

    #pragma unroll
    for (int k = 3; k <= 8; k++) {
        double ck = c[9 - k];
        double s[8];
        #pragma unroll
        for (int j = 0; j < 8; j++) s[j] = (lane == j) ? ck : 0.0;
        #pragma unroll
        for (int t = 0; t < 8; t++) {
            double w = Asr[t];
            #pragma unroll
            for (int j = 0; j < 8; j++) s[j] += w * Mg[t * 9 + j];
        }
        double tr = 0.0;
        #pragma unroll
        for (int j = 0; j < 8; j++) tr += Asr[j] * s[j];
        c[8 - k] = -dred(tr) / (double)k;
        #pragma unroll
        for (int j = 0; j < 8; j++) Mrows[k - 2][j] = s[j];
        __syncwarp();
        if (k < 8) {
            #pragma unroll
            for (int j = 0; j < 8; j++) Mg[lane * 9 + j] = s[j];
        }
        __syncwarp();
    }

    double rootmine = g_roots[(size_t)bb * 8 + lane];
    float  frmine   = g_fs[(size_t)bb * 16 + lane];
    float  stmine   = g_fs[(size_t)bb * 16 + 8 + lane];

    float Vrow[8];
    #pragma unroll 1
    for (int i = 0; i < 8; i++) {
        double lam = dshfl(rootmine, i);
        double rcol[8];
        #pragma unroll
        for (int col = 0; col < 8; col++) {
            double r = (lane == col) ? 1.0 : 0.0;
            #pragma unroll
            for (int s = 0; s < 7; s++)
                r = r * lam + Mrows[s][col];
            rcol[col] = r;
        }
        double cn[8];
        #pragma unroll
        for (int col = 0; col < 8; col++) cn[col] = dred(rcol[col] * rcol[col]);
        int best = 0; double bv = cn[0];
        #pragma unroll
        for (int col = 1; col < 8; col++)
            if (cn[col] > bv) { bv = cn[col]; best = col; }
        double v = rcol[0];
        #pragma unroll
        for (int col = 1; col < 8; col++) if (best == col) v = rcol[col];
        double s2 = dred(v * v);
        double nrm = sqrt(s2) + 1e-30;
        Vrow[i] = (float)(v / nrm);
    }

    #pragma unroll
    for (int j = 0; j < 8; j++) Fg[lane * 9 + j] = Vrow[j];
    __syncwarp();
    float Yrow[8], Xrow[8];
    #pragma unroll
    for (int j = 0; j < 8; j++) { Yrow[j] = 0.f; Xrow[j] = (lane == j) ? 1.f : 0.f; }
    #pragma unroll
    for (int a = 0; a < 8; a++) {
        float vai = Fg[a * 9 + lane];
        #pragma unroll
        for (int j = 0; j < 8; j++) Yrow[j] += vai * Fg[a * 9 + j];
    }

    #pragma unroll 1
    for (int ns = 0; ns < 2; ns++) {
        float Trow[8], Xn[8], Yn[8];
        #pragma unroll
        for (int j = 0; j < 8; j++) {
            Trow[j] = ((lane == j) ? 3.f : 0.f) - Yrow[j];
            Xn[j] = 0.f; Yn[j] = 0.f;
        }
        #pragma unroll
        for (int kk = 0; kk < 8; kk++) {
            float xk = Xrow[kk];
            float tk = Trow[kk];
            #pragma unroll
            for (int j = 0; j < 8; j++) {
                float tkj = fshfl(Trow[j], kk);
                float ykj = fshfl(Yrow[j], kk);
                Xn[j] += xk * tkj;
                Yn[j] += tk * ykj;
            }
        }
        #pragma unroll
        for (int j = 0; j < 8; j++) { Xrow[j] = 0.5f * Xn[j]; Yrow[j] = 0.5f * Yn[j]; }
    }
    {
        float Vn[8];
        #pragma unroll
        for (int j = 0; j < 8; j++) Vn[j] = 0.f;
        #pragma unroll
        for (int kk = 0; kk < 8; kk++) {
            float vk = Vrow[kk];
            #pragma unroll
            for (int j = 0; j < 8; j++) Vn[j] += vk * fshfl(Xrow[j], kk);
        }
        #pragma unroll
        for (int j = 0; j < 8; j++) Vrow[j] = Vn[j];
    }

    __syncwarp();
    #pragma unroll
    for (int j = 0; j < 8; j++) Fg[lane * 9 + j] = Vrow[j];
    __syncwarp();

    float rrp = 0.f;
    #pragma unroll
    for (int j = 0; j < 8; j++) {
        float s = 0.f;
        #pragma unroll
        for (int a = 0; a < 8; a++) s += Fg[a * 9 + lane] * Fg[a * 9 + j];
        float d = s - ((lane == j) ? 1.f : 0.f);
        rrp += d * d;
    }
    float rr = sqrtf(fred(rrp));

    float evals[8];
    #pragma unroll
    for (int i = 0; i < 8; i++) {
        float av = 0.f;
        #pragma unroll
        for (int k = 0; k < 8; k++) av += Afr[k] * Fg[k * 9 + i];
        evals[i] = fred(Vrow[i] * av);
    }

    int perm[8];
    #pragma unroll
    for (int i = 0; i < 8; i++) perm[i] = i;
    #pragma unroll 1
    for (int i = 1; i < 8; i++) {
        int key = perm[i];
        float kv = evals[key];
        int j = i - 1;
        while (j >= 0 && evals[perm[j]] > kv) { perm[j + 1] = perm[j]; j--; }
        perm[j + 1] = key;
    }

    if (b < B) {
        size_t Bs = (size_t)B;
        float* o_se = out;
        float* o_sv = out + Bs * 8;
        float* o_fr = out + Bs * 80;
        float* o_st = out + Bs * 88;
        float* o_eo = out + Bs * 96;
        float* o_rr = out + Bs * 104;

        int p = perm[lane];
        o_se[(size_t)b * 8 + lane] = evals[p];
        o_fr[(size_t)b * 8 + lane] = __shfl_sync(FULLM, frmine, p, 8);
        o_st[(size_t)b * 8 + lane] = __shfl_sync(FULLM, stmine, p, 8);
        o_eo[(size_t)b * 8 + lane] = (float)lane;
        if (lane == 0) o_rr[b] = rr;

        float outv[8];
        #pragma unroll
        for (int i = 0; i < 8; i++) {
            int pi = perm[i];
            float myv = Fg[lane * 9 + pi];
            float bvv = 0.f, sval = 0.f;
            #pragma unroll
            for (int a = 0; a < 8; a++) {
                float v = Fg[a * 9 + pi];
                float avv = fabsf(v);
                if (avv > bvv) { bvv = avv; sval = v; }
            }
            float sg = (sval > 0.f) ? 1.f : ((sval < 0.f) ? -1.f : 0.f);
            outv[i] = myv * sg;
        }
        float4* dst = (float4*)(o_sv + (size_t)b * 64 + lane * 8);
        dst[0] = make_float4(outv[0], outv[1], outv[2], outv[3]);
        dst[1] = make_float4(outv[4], outv[5], outv[6], outv[7]);
    }
}

extern "C" void kernel_launch(void* const* d_in, const int* in_sizes, int n_in,
                              void* d_out, int out_size)
{
    const float* A = (const float*)d_in[0];
    float* out = (float*)d_out;
    int B = in_sizes[0] / 64;
    int gblocks = (B + GPB - 1) / GPB;
    k1_fl<<<gblocks, THREADS>>>(A, out, B);
    k2_lag<<<(B + 127) / 128, 128>>>(B);
    k3_vec<<<gblocks, THREADS>>>(A, out, B);
}

// round 9
// speedup vs baseline: 2.6009x; 1.4391x over previous
#include <cuda_runtime.h>
#include <math.h>

#define LAGI 5
#define POLI 3
#define BMAX 65536
#define GPB 16
#define THREADS 128
#define FULLM 0xffffffffu

__device__ double g_c[BMAX * 9];
__device__ double g_zi[BMAX * 8];
__device__ double g_roots[BMAX * 8];
__device__ float  g_fs[BMAX * 16];
__device__ double g_M[(size_t)BMAX * 448];   // M2..M8, [b][k2][i][j]

__device__ __forceinline__ double dshfl(double v, int s) {
    return __shfl_sync(FULLM, v, s, 8);
}
__device__ __forceinline__ double dred(double v) {
    v += __shfl_xor_sync(FULLM, v, 4, 8);
    v += __shfl_xor_sync(FULLM, v, 2, 8);
    v += __shfl_xor_sync(FULLM, v, 1, 8);
    return v;
}
__device__ __forceinline__ float fshfl(float v, int s) {
    return __shfl_sync(FULLM, v, s, 8);
}
__device__ __forceinline__ float fred(float v) {
    v += __shfl_xor_sync(FULLM, v, 4, 8);
    v += __shfl_xor_sync(FULLM, v, 2, 8);
    v += __shfl_xor_sync(FULLM, v, 1, 8);
    return v;
}

// ============================================================
// K1: Faddeev-LeVerrier (8 lanes/batch) -> c, zi, char_coeffs, g_M
// ============================================================
__global__ void __launch_bounds__(THREADS)
k1_fl(const float* __restrict__ Aall, float* __restrict__ out, int B)
{
    __shared__ double Msh[GPB][72];

    int tid = threadIdx.x, lane = tid & 7, grp = tid >> 3;
    int b = blockIdx.x * GPB + grp;
    int bb = (b < B) ? b : (B - 1);
    const float* Ap = Aall + (size_t)bb * 64;
    double* Mg = Msh[grp];

    float nrm2 = 0.f;
    #pragma unroll
    for (int i = 0; i < 64; i++) {
        float v = Ap[i];
        nrm2 = __fadd_rn(nrm2, __fmul_rn(v, v));
    }
    double scale = (double)sqrtf(nrm2) / 2.8284271247461903;
    scale = fmax(scale, 1e-12);
    double rscale = 1.0 / scale;

    double Asr[8];
    {
        const float4* Ap4 = (const float4*)(Ap + lane * 8);
        float4 q0 = Ap4[0], q1 = Ap4[1];
        Asr[0] = (double)q0.x * rscale; Asr[1] = (double)q0.y * rscale;
        Asr[2] = (double)q0.z * rscale; Asr[3] = (double)q0.w * rscale;
        Asr[4] = (double)q1.x * rscale; Asr[5] = (double)q1.y * rscale;
        Asr[6] = (double)q1.z * rscale; Asr[7] = (double)q1.w * rscale;
    }

    double c[9];
    #pragma unroll
    for (int i = 0; i < 9; i++) c[i] = 0.0;
    c[8] = 1.0;

    double dmine = 0.0;
    #pragma unroll
    for (int j = 0; j < 8; j++) if (lane == j) dmine = Asr[j];
    c[7] = -dred(dmine);

    {
        double tr = 0.0;
        #pragma unroll
        for (int j = 0; j < 8; j++) {
            double v = Asr[j] + ((lane == j) ? c[7] : 0.0);
            Mg[lane * 9 + j] = v;
            tr = fma(Asr[j], v, tr);
        }
        c[6] = -dred(tr) / 2.0;
        if (b < B) {
            double* gm = g_M + (size_t)b * 448 + lane * 8;
            #pragma unroll
            for (int j = 0; j < 8; j++) gm[j] = Mg[lane * 9 + j];
        }
    }
    __syncwarp();

    #pragma unroll 1
    for (int k = 3; k <= 8; k++) {
        double ck = c[9 - k];
        double s[8];
        #pragma unroll
        for (int j = 0; j < 8; j++) s[j] = (lane == j) ? ck : 0.0;
        #pragma unroll
        for (int t = 0; t < 8; t++) {
            double w = Asr[t];
            #pragma unroll
            for (int j = 0; j < 8; j++) s[j] = fma(w, Mg[t * 9 + j], s[j]);
        }
        double tr = 0.0;
        #pragma unroll
        for (int j = 0; j < 8; j++) tr = fma(Asr[j], s[j], tr);
        c[8 - k] = -dred(tr) / (double)k;
        if (b < B) {
            double* gm = g_M + (size_t)b * 448 + (size_t)(k - 2) * 64 + lane * 8;
            #pragma unroll
            for (int j = 0; j < 8; j++) gm[j] = s[j];
        }
        __syncwarp();
        #pragma unroll
        for (int j = 0; j < 8; j++) Mg[lane * 9 + j] = s[j];
        __syncwarp();
    }

    double zi[8];
    #pragma unroll
    for (int i = 0; i < 8; i++) zi[i] = dshfl(dmine, i);
    #pragma unroll 1
    for (int i = 1; i < 8; i++) {
        double key = zi[i];
        int j = i - 1;
        while (j >= 0 && zi[j] > key) { zi[j + 1] = zi[j]; j--; }
        zi[j + 1] = key;
    }

    if (b < B && lane == 0) {
        #pragma unroll
        for (int i = 0; i < 9; i++) g_c[(size_t)b * 9 + i] = c[i];
        #pragma unroll
        for (int i = 0; i < 8; i++) g_zi[(size_t)b * 8 + i] = zi[i];
        float* o_cc = out + (size_t)B * 72;
        #pragma unroll
        for (int i = 0; i < 8; i++) o_cc[(size_t)b * 8 + i] = (float)c[i];
    }
}

// ============================================================
// K2: Laguerre + deflation + polish (1 thread/batch, f64 FMA)
// ============================================================
__global__ void __launch_bounds__(128)
k2_lag(int B)
{
    int b = blockIdx.x * blockDim.x + threadIdx.x;
    if (b >= B) return;

    double c[9], cl[9], zi[8];
    #pragma unroll
    for (int i = 0; i < 9; i++) { c[i] = g_c[(size_t)b * 9 + i]; cl[i] = c[i]; }
    #pragma unroll
    for (int i = 0; i < 8; i++) zi[i] = g_zi[(size_t)b * 8 + i];

    const double lstep = 2e-4 / 7.0;
    double roots[8];
    float fric[8], sett[8];

    #pragma unroll
    for (int ri = 0; ri < 8; ri++) {
        const int deg = 8 - ri;
        const double dd = (double)deg;
        double z = zi[ri] + (-1e-4 + lstep * (double)ri);
        float fr = 0.f, st = (float)LAGI;
        #pragma unroll
        for (int it = 0; it < LAGI; it++) {
            double pv = cl[deg], dp = 0.0, d2 = 0.0;
            #pragma unroll
            for (int j = deg - 1; j >= 0; j--) {
                d2 = fma(d2, z, dp);
                dp = fma(dp, z, pv);
                pv = fma(pv, z, cl[j]);
            }
            float dp_abs = (float)fabs(dp);
            fr = __fadd_rn(fr, 1.0f / __fadd_rn(dp_abs, 1e-8f));
            float pv_abs = (float)fabs(pv);
            if (pv_abs < 1e-6f && st == (float)LAGI) st = (float)it;
            bool ok = fabs(pv) > 1e-30;
            double ps = ok ? pv : 1.0;
            double rps = 1.0 / ps;
            double G = ok ? (dp * rps) : 0.0;
            double GG = G * G;
            double twod2 = ok ? (2.0 * d2 * rps) : 0.0;
            double H = GG - twod2;
            double inner = fma(dd, H, -GG);
            double disc = (dd - 1.0) * inner;
            disc = disc > 0.0 ? disc : 0.0;
            double sq = sqrt(disc);
            double gp = G + sq, gm = G - sq;
            double den = (fabs(gp) >= fabs(gm)) ? gp : gm;
            bool dok = fabs(den) > 1e-20;
            double ds = dok ? den : 1.0;
            z = z - (dok ? (dd / ds) : 0.0);
        }
        roots[ri] = z; fric[ri] = fr; sett[ri] = st;
        double bcur = cl[deg];
        #pragma unroll
        for (int j = deg - 1; j >= 1; j--) {
            double tmp = cl[j];
            cl[j] = bcur;
            bcur = fma(z, bcur, tmp);
        }
        cl[0] = bcur;
    }

    #pragma unroll
    for (int p = 0; p < POLI; p++) {
        #pragma unroll
        for (int i = 0; i < 8; i++) {
            double r = roots[i];
            double pv = 1.0, dp = 0.0;
            #pragma unroll
            for (int j = 7; j >= 0; j--) {
                dp = fma(dp, r, pv);
                pv = fma(pv, r, c[j]);
            }
            if (fabs(dp) > 1e-30) r = r - pv / dp;
            roots[i] = r;
        }
    }

    #pragma unroll
    for (int i = 0; i < 8; i++) g_roots[(size_t)b * 8 + i] = roots[i];
    #pragma unroll
    for (int i = 0; i < 8; i++) {
        g_fs[(size_t)b * 16 + i]     = fric[i];
        g_fs[(size_t)b * 16 + 8 + i] = sett[i];
    }
}

// ============================================================
// K3: eigvecs from stored M (f32 norms, f64 best col) + NS + outputs
// ============================================================
__global__ void __launch_bounds__(THREADS)
k3_vec(const float* __restrict__ Aall, float* __restrict__ out, int B)
{
    __shared__ float Msf[GPB][7][72];   // f32 copy of M2..M8, row stride 9
    __shared__ float Fsh[GPB][72];

    int tid = threadIdx.x, lane = tid & 7, grp = tid >> 3;
    int b = blockIdx.x * GPB + grp;
    int bb = (b < B) ? b : (B - 1);
    const float* Ap = Aall + (size_t)bb * 64;
    float* Fg = Fsh[grp];

    // cooperative load g_M -> f32 smem (also warms L1/L2 for the f64 reads)
    for (int r = tid; r < GPB * 56; r += THREADS) {
        int g_ = r / 56, rem = r % 56, k2 = rem / 8, i = rem % 8;
        int bs = blockIdx.x * GPB + g_;
        if (bs >= B) bs = B - 1;
        const double* src = g_M + (size_t)bs * 448 + (size_t)k2 * 64 + i * 8;
        float* dst = &Msf[g_][k2][i * 9];
        #pragma unroll
        for (int j = 0; j < 8; j++) dst[j] = (float)src[j];
    }
    __syncthreads();

    double rootmine = g_roots[(size_t)bb * 8 + lane];
    float  rootfmine = (float)rootmine;
    float  frmine   = g_fs[(size_t)bb * 16 + lane];
    float  stmine   = g_fs[(size_t)bb * 16 + 8 + lane];

    const double* gMb = g_M + (size_t)bb * 448;

    float Vrow[8];
    #pragma unroll 1
    for (int i = 0; i < 8; i++) {
        float lamf = fshfl(rootfmine, i);
        // f32 column norm for column = lane
        float cn = 0.f;
        #pragma unroll
        for (int a = 0; a < 8; a++) {
            float r = (a == lane) ? 1.f : 0.f;
            #pragma unroll
            for (int k2 = 0; k2 < 7; k2++)
                r = fmaf(r, lamf, Msf[grp][k2][a * 9 + lane]);
            cn = fmaf(r, r, cn);
        }
        // argmax over 8 lanes (first max wins)
        float bval = cn; int bidx = lane;
        #pragma unroll
        for (int off = 1; off < 8; off <<= 1) {
            float ov = __shfl_xor_sync(FULLM, bval, off, 8);
            int   oi = __shfl_xor_sync(FULLM, bidx, off, 8);
            if (ov > bval || (ov == bval && oi < bidx)) { bval = ov; bidx = oi; }
        }
        int best = bidx;
        // f64 Horner for the winning column (lane = row)
        double lam = dshfl(rootmine, i);
        double rv = (lane == best) ? 1.0 : 0.0;
        #pragma unroll
        for (int k2 = 0; k2 < 7; k2++)
            rv = fma(rv, lam, gMb[(size_t)k2 * 64 + lane * 8 + best]);
        float vf = (float)rv;
        float s2 = fred(vf * vf);
        float nrm = sqrtf(s2) + 1e-30f;
        Vrow[i] = vf / nrm;
    }

    #pragma unroll
    for (int j = 0; j < 8; j++) Fg[lane * 9 + j] = Vrow[j];
    __syncwarp();
    float Yrow[8], Xrow[8];
    #pragma unroll
    for (int j = 0; j < 8; j++) { Yrow[j] = 0.f; Xrow[j] = (lane == j) ? 1.f : 0.f; }
    #pragma unroll
    for (int a = 0; a < 8; a++) {
        float vai = Fg[a * 9 + lane];
        #pragma unroll
        for (int j = 0; j < 8; j++) Yrow[j] += vai * Fg[a * 9 + j];
    }

    #pragma unroll 1
    for (int ns = 0; ns < 2; ns++) {
        float Trow[8], Xn[8], Yn[8];
        #pragma unroll
        for (int j = 0; j < 8; j++) {
            Trow[j] = ((lane == j) ? 3.f : 0.f) - Yrow[j];
            Xn[j] = 0.f; Yn[j] = 0.f;
        }
        #pragma unroll
        for (int kk = 0; kk < 8; kk++) {
            float xk = Xrow[kk];
            float tk = Trow[kk];
            #pragma unroll
            for (int j = 0; j < 8; j++) {
                float tkj = fshfl(Trow[j], kk);
                float ykj = fshfl(Yrow[j], kk);
                Xn[j] += xk * tkj;
                Yn[j] += tk * ykj;
            }
        }
        #pragma unroll
        for (int j = 0; j < 8; j++) { Xrow[j] = 0.5f * Xn[j]; Yrow[j] = 0.5f * Yn[j]; }
    }
    {
        float Vn[8];
        #pragma unroll
        for (int j = 0; j < 8; j++) Vn[j] = 0.f;
        #pragma unroll
        for (int kk = 0; kk < 8; kk++) {
            float vk = Vrow[kk];
            #pragma unroll
            for (int j = 0; j < 8; j++) Vn[j] += vk * fshfl(Xrow[j], kk);
        }
        #pragma unroll
        for (int j = 0; j < 8; j++) Vrow[j] = Vn[j];
    }

    __syncwarp();
    #pragma unroll
    for (int j = 0; j < 8; j++) Fg[lane * 9 + j] = Vrow[j];
    __syncwarp();

    float rrp = 0.f;
    #pragma unroll
    for (int j = 0; j < 8; j++) {
        float s = 0.f;
        #pragma unroll
        for (int a = 0; a < 8; a++) s += Fg[a * 9 + lane] * Fg[a * 9 + j];
        float d = s - ((lane == j) ? 1.f : 0.f);
        rrp += d * d;
    }
    float rr = sqrtf(fred(rrp));

    float Afr[8];
    {
        const float4* Ap4 = (const float4*)(Ap + lane * 8);
        float4 q0 = Ap4[0], q1 = Ap4[1];
        Afr[0] = q0.x; Afr[1] = q0.y; Afr[2] = q0.z; Afr[3] = q0.w;
        Afr[4] = q1.x; Afr[5] = q1.y; Afr[6] = q1.z; Afr[7] = q1.w;
    }
    float evals[8];
    #pragma unroll
    for (int i = 0; i < 8; i++) {
        float av = 0.f;
        #pragma unroll
        for (int k = 0; k < 8; k++) av += Afr[k] * Fg[k * 9 + i];
        evals[i] = fred(Vrow[i] * av);
    }

    int perm[8];
    #pragma unroll
    for (int i = 0; i < 8; i++) perm[i] = i;
    #pragma unroll 1
    for (int i = 1; i < 8; i++) {
        int key = perm[i];
        float kv = evals[key];
        int j = i - 1;
        while (j >= 0 && evals[perm[j]] > kv) { perm[j + 1] = perm[j]; j--; }
        perm[j + 1] = key;
    }

    if (b < B) {
        size_t Bs = (size_t)B;
        float* o_se = out;
        float* o_sv = out + Bs * 8;
        float* o_fr = out + Bs * 80;
        float* o_st = out + Bs * 88;
        float* o_eo = out + Bs * 96;
        float* o_rr = out + Bs * 104;

        int p = perm[lane];
        o_se[(size_t)b * 8 + lane] = evals[p];
        o_fr[(size_t)b * 8 + lane] = __shfl_sync(FULLM, frmine, p, 8);
        o_st[(size_t)b * 8 + lane] = __shfl_sync(FULLM, stmine, p, 8);
        o_eo[(size_t)b * 8 + lane] = (float)lane;
        if (lane == 0) o_rr[b] = rr;

        float outv[8];
        #pragma unroll
        for (int i = 0; i < 8; i++) {
            int pi = perm[i];
            float myv = Fg[lane * 9 + pi];
            float bvv = 0.f, sval = 0.f;
            #pragma unroll
            for (int a = 0; a < 8; a++) {
                float v = Fg[a * 9 + pi];
                float avv = fabsf(v);
                if (avv > bvv) { bvv = avv; sval = v; }
            }
            float sg = (sval > 0.f) ? 1.f : ((sval < 0.f) ? -1.f : 0.f);
            outv[i] = myv * sg;
        }
        float4* dst = (float4*)(o_sv + (size_t)b * 64 + lane * 8);
        dst[0] = make_float4(outv[0], outv[1], outv[2], outv[3]);
        dst[1] = make_float4(outv[4], outv[5], outv[6], outv[7]);
    }
}

extern "C" void kernel_launch(void* const* d_in, const int* in_sizes, int n_in,
                              void* d_out, int out_size)
{
    const float* A = (const float*)d_in[0];
    float* out = (float*)d_out;
    int B = in_sizes[0] / 64;
    int gblocks = (B + GPB - 1) / GPB;
    k1_fl<<<gblocks, THREADS>>>(A, out, B);
    k2_lag<<<(B + 127) / 128, 128>>>(B);
    k3_vec<<<gblocks, THREADS>>>(A, out, B);
}